// round 5
// baseline (speedup 1.0000x reference)
#include <cuda_runtime.h>
#include <cstdint>
#include <mma.h>

using namespace nvcuda;

#define NEMBD 1024
#define TT 128
#define HS 128
#define NB 256

// Scratch (device globals; no allocations allowed).
__device__ float g_q[(size_t)NB * TT * HS];
__device__ float g_k[(size_t)NB * TT * HS];
__device__ float g_v[(size_t)NB * TT * HS];
__device__ float g_wc[(size_t)3 * NEMBD * HS];    // Wq|Wk|Wv, RN-rounded to tf32

// ---------------------------------------------------------------------------
// Pre-pass: RN-round W fp32 -> tf32 (x is now converted in-smem in the GEMM).
// ---------------------------------------------------------------------------
__global__ void conv_w_kernel(const float* __restrict__ wq,
                              const float* __restrict__ wk,
                              const float* __restrict__ wv)
{
    const int n4 = NEMBD * HS / 4;   // per weight
    int stride = gridDim.x * blockDim.x;
    for (int i = blockIdx.x * blockDim.x + threadIdx.x; i < 3 * n4; i += stride) {
        int w = i / n4, j = i % n4;
        const float* src = (w == 0) ? wq : (w == 1) ? wk : wv;
        float4 v = reinterpret_cast<const float4*>(src)[j];
        v.x = wmma::__float_to_tf32(v.x);
        v.y = wmma::__float_to_tf32(v.y);
        v.z = wmma::__float_to_tf32(v.z);
        v.w = wmma::__float_to_tf32(v.w);
        reinterpret_cast<float4*>(g_wc)[i] = v;
    }
}

// ---------------------------------------------------------------------------
// QKV GEMM + RoPE. Grid (3 weights, 128 row-pairs). CTA tile: 256 rows x 128
// cols, 512 threads / 16 warps (4x4), warp tile 64x32.
// 4-buffer cp.async pipeline (3 deep); A is raw fp32 from x, RN-converted to
// tf32 in-smem after each stage arrives.
// ---------------------------------------------------------------------------
static constexpr int AS_LD = 36;                      // 256 x 36
static constexpr int BS_LD = 132;                     // 32 x 132
static constexpr int A_FL  = 256 * AS_LD;             // 9216
static constexpr int B_FL  = 32 * BS_LD;              // 4224
static constexpr int ST_FL = A_FL + B_FL;             // 13440 floats / stage
static constexpr int NBUF  = 4;
static constexpr int QKV_SMEM = NBUF * ST_FL * 4;     // 215040 B

__device__ __forceinline__ void cp_async16(uint32_t saddr, const float* gptr)
{
    asm volatile("cp.async.cg.shared.global [%0], [%1], 16;\n"
                 :: "r"(saddr), "l"(gptr));
}

__global__ void __launch_bounds__(512)
qkv_rope_kernel(const float* __restrict__ x)
{
    extern __shared__ float smem[];
    const int w    = blockIdx.x;          // 0=q 1=k 2=v
    const int b2   = blockIdx.y;          // rows b2*256 .. +255
    const int tid  = threadIdx.x;
    const int warp = tid >> 5;
    const int wm   = warp >> 2;           // 0..3 -> 64-row band
    const int wn   = warp & 3;            // 0..3 -> 32-col band

    const float* xbase = x + (size_t)b2 * 256 * NEMBD;
    const float* wbase = g_wc + (size_t)w * NEMBD * HS;

    wmma::fragment<wmma::accumulator, 16, 16, 8, float> acc[4][2];
    #pragma unroll
    for (int i = 0; i < 4; i++)
        #pragma unroll
        for (int j = 0; j < 2; j++)
            wmma::fill_fragment(acc[i][j], 0.0f);

    auto load_stage = [&](int stage) {      // stage index 0..31
        float* As = smem + (stage & 3) * ST_FL;
        float* Bs = As + A_FL;
        int k0 = stage * 32;
        // A: 256 x 32 floats = 2048 float4, 4 per thread (raw fp32 x)
        #pragma unroll
        for (int j = 0; j < 4; j++) {
            int idx = tid + j * 512;
            int r = idx >> 3, c4 = idx & 7;
            uint32_t sa = (uint32_t)__cvta_generic_to_shared(As + r * AS_LD + c4 * 4);
            cp_async16(sa, xbase + (size_t)r * NEMBD + k0 + c4 * 4);
        }
        // B: 32 x 128 floats = 1024 float4, 2 per thread (pre-converted tf32)
        #pragma unroll
        for (int j = 0; j < 2; j++) {
            int idx = tid + j * 512;
            int r = idx >> 5, c4 = idx & 31;
            uint32_t sa = (uint32_t)__cvta_generic_to_shared(Bs + r * BS_LD + c4 * 4);
            cp_async16(sa, wbase + (size_t)(k0 + r) * HS + c4 * 4);
        }
    };

    load_stage(0); asm volatile("cp.async.commit_group;\n");
    load_stage(1); asm volatile("cp.async.commit_group;\n");
    load_stage(2); asm volatile("cp.async.commit_group;\n");

    for (int it = 0; it < 32; ++it) {
        asm volatile("cp.async.wait_group 2;\n");
        __syncthreads();

        float* As = smem + (it & 3) * ST_FL;
        const float* Bs = As + A_FL;

        // RN-convert the freshly arrived A stage (raw fp32 -> tf32) in place.
        #pragma unroll
        for (int j = 0; j < 4; j++) {
            int idx = tid + j * 512;
            int r = idx >> 3, c4 = idx & 7;
            float4* p = reinterpret_cast<float4*>(As + r * AS_LD + c4 * 4);
            float4 v = *p;
            v.x = wmma::__float_to_tf32(v.x);
            v.y = wmma::__float_to_tf32(v.y);
            v.z = wmma::__float_to_tf32(v.z);
            v.w = wmma::__float_to_tf32(v.w);
            *p = v;
        }
        __syncthreads();

        #pragma unroll
        for (int kk = 0; kk < 32; kk += 8) {
            wmma::fragment<wmma::matrix_a, 16, 16, 8, wmma::precision::tf32, wmma::row_major> af[4];
            wmma::fragment<wmma::matrix_b, 16, 16, 8, wmma::precision::tf32, wmma::row_major> bf[2];
            #pragma unroll
            for (int i = 0; i < 4; i++)
                wmma::load_matrix_sync(af[i], As + (wm * 64 + i * 16) * AS_LD + kk, AS_LD);
            #pragma unroll
            for (int j = 0; j < 2; j++)
                wmma::load_matrix_sync(bf[j], Bs + kk * BS_LD + wn * 32 + j * 16, BS_LD);
            #pragma unroll
            for (int i = 0; i < 4; i++)
                #pragma unroll
                for (int j = 0; j < 2; j++)
                    wmma::mma_sync(acc[i][j], af[i], bf[j], acc[i][j]);
        }

        if (it + 3 < 32) load_stage(it + 3);
        asm volatile("cp.async.commit_group;\n");   // empty group OK
    }

    asm volatile("cp.async.wait_group 0;\n");
    __syncthreads();

    // Park C (256 x 128) in smem (reuses pipeline buffers).
    float* Cs = smem;
    #pragma unroll
    for (int i = 0; i < 4; i++)
        #pragma unroll
        for (int j = 0; j < 2; j++)
            wmma::store_matrix_sync(Cs + (wm * 64 + i * 16) * HS + wn * 32 + j * 16,
                                    acc[i][j], HS, wmma::mem_row_major);
    __syncthreads();

    float* outb = ((w == 0) ? g_q : (w == 1) ? g_k : g_v) + (size_t)b2 * 256 * HS;

    if (w == 2) {
        for (int i = tid; i < 256 * HS / 4; i += 512)
            reinterpret_cast<float4*>(outb)[i] = reinterpret_cast<const float4*>(Cs)[i];
    } else {
        const float qscale = (w == 0) ? 0.08838834764831845f : 1.0f;  // 1/sqrt(128)
        const float nlt = -logf(10000.0f) * (2.0f / 128.0f);
        for (int idx = tid; idx < 256 * 64; idx += 512) {   // pair index
            int r = idx >> 6;            // 0..255
            int p = idx & 63;
            int t = r & 127;             // position within sequence
            float inv_freq = __expf(nlt * (float)p);
            float ang = (float)t * inv_freq;
            float s, c;
            sincosf(ang, &s, &c);
            float cr = Cs[r * HS + 2 * p];
            float ci = Cs[r * HS + 2 * p + 1];
            outb[r * HS + 2 * p]     = (cr * c - ci * s) * qscale;
            outb[r * HS + 2 * p + 1] = (cr * s + ci * c) * qscale;
        }
    }
}

// ---------------------------------------------------------------------------
// Kernel 2: per-batch attention, 512 threads / 16 warps (4x4), warp tile
// 32x32. Warp-parallel softmax (8 rows per warp).
// ---------------------------------------------------------------------------
__global__ void __launch_bounds__(512)
attn_kernel(float* __restrict__ out)
{
    extern __shared__ float smem[];
    float* sq = smem;            // [128][128], later S/P
    float* sk = smem + 16384;
    float* sv = smem + 32768;

    const int b    = blockIdx.x;
    const int tid  = threadIdx.x;
    const int warp = tid >> 5;
    const int lane = tid & 31;
    const int wm   = warp >> 2;   // 0..3 -> 32-row band
    const int wn   = warp & 3;    // 0..3 -> 32-col band

    const float* gq = g_q + (size_t)b * TT * HS;
    const float* gk = g_k + (size_t)b * TT * HS;
    const float* gv = g_v + (size_t)b * TT * HS;

    for (int i = tid; i < 4096; i += 512) {
        float4 a = reinterpret_cast<const float4*>(gq)[i];
        float4 c = reinterpret_cast<const float4*>(gk)[i];
        float4 d = reinterpret_cast<const float4*>(gv)[i];
        float* pq = sq + i * 4;
        float* pk = sk + i * 4;
        float* pv = sv + i * 4;
        pq[0] = wmma::__float_to_tf32(a.x); pq[1] = wmma::__float_to_tf32(a.y);
        pq[2] = wmma::__float_to_tf32(a.z); pq[3] = wmma::__float_to_tf32(a.w);
        pk[0] = wmma::__float_to_tf32(c.x); pk[1] = wmma::__float_to_tf32(c.y);
        pk[2] = wmma::__float_to_tf32(c.z); pk[3] = wmma::__float_to_tf32(c.w);
        pv[0] = wmma::__float_to_tf32(d.x); pv[1] = wmma::__float_to_tf32(d.y);
        pv[2] = wmma::__float_to_tf32(d.z); pv[3] = wmma::__float_to_tf32(d.w);
    }
    __syncthreads();

    wmma::fragment<wmma::accumulator, 16, 16, 8, float> acc[2][2];
    #pragma unroll
    for (int i = 0; i < 2; i++)
        #pragma unroll
        for (int j = 0; j < 2; j++)
            wmma::fill_fragment(acc[i][j], 0.0f);

    #pragma unroll
    for (int kk = 0; kk < HS; kk += 8) {
        wmma::fragment<wmma::matrix_a, 16, 16, 8, wmma::precision::tf32, wmma::row_major> af[2];
        wmma::fragment<wmma::matrix_b, 16, 16, 8, wmma::precision::tf32, wmma::col_major> bf[2];
        #pragma unroll
        for (int i = 0; i < 2; i++)
            wmma::load_matrix_sync(af[i], sq + (wm * 32 + i * 16) * HS + kk, HS);
        #pragma unroll
        for (int j = 0; j < 2; j++)
            wmma::load_matrix_sync(bf[j], sk + (wn * 32 + j * 16) * HS + kk, HS);
        #pragma unroll
        for (int i = 0; i < 2; i++)
            #pragma unroll
            for (int j = 0; j < 2; j++)
                wmma::mma_sync(acc[i][j], af[i], bf[j], acc[i][j]);
    }
    __syncthreads();

    #pragma unroll
    for (int i = 0; i < 2; i++)
        #pragma unroll
        for (int j = 0; j < 2; j++)
            wmma::store_matrix_sync(sq + (wm * 32 + i * 16) * HS + wn * 32 + j * 16,
                                    acc[i][j], HS, wmma::mem_row_major);
    __syncthreads();

    // Warp-parallel causal softmax: each warp handles 8 rows.
    #pragma unroll 1
    for (int rr = 0; rr < 8; rr++) {
        const int t = warp * 8 + rr;
        float4 v4 = reinterpret_cast<float4*>(sq + t * HS)[lane];
        const int c0 = lane * 4;

        float m = -1e30f;
        if (c0 + 0 <= t) m = fmaxf(m, v4.x);
        if (c0 + 1 <= t) m = fmaxf(m, v4.y);
        if (c0 + 2 <= t) m = fmaxf(m, v4.z);
        if (c0 + 3 <= t) m = fmaxf(m, v4.w);
        #pragma unroll
        for (int off = 16; off > 0; off >>= 1)
            m = fmaxf(m, __shfl_xor_sync(0xffffffffu, m, off));

        float e0 = (c0 + 0 <= t) ? __expf(v4.x - m) : 0.0f;
        float e1 = (c0 + 1 <= t) ? __expf(v4.y - m) : 0.0f;
        float e2 = (c0 + 2 <= t) ? __expf(v4.z - m) : 0.0f;
        float e3 = (c0 + 3 <= t) ? __expf(v4.w - m) : 0.0f;
        float s = e0 + e1 + e2 + e3;
        #pragma unroll
        for (int off = 16; off > 0; off >>= 1)
            s += __shfl_xor_sync(0xffffffffu, s, off);

        float inv = 1.0f / s;
        v4.x = wmma::__float_to_tf32(e0 * inv);
        v4.y = wmma::__float_to_tf32(e1 * inv);
        v4.z = wmma::__float_to_tf32(e2 * inv);
        v4.w = wmma::__float_to_tf32(e3 * inv);
        reinterpret_cast<float4*>(sq + t * HS)[lane] = v4;
    }
    __syncthreads();

    #pragma unroll
    for (int i = 0; i < 2; i++)
        #pragma unroll
        for (int j = 0; j < 2; j++)
            wmma::fill_fragment(acc[i][j], 0.0f);

    #pragma unroll
    for (int kk = 0; kk < TT; kk += 8) {
        wmma::fragment<wmma::matrix_a, 16, 16, 8, wmma::precision::tf32, wmma::row_major> af[2];
        wmma::fragment<wmma::matrix_b, 16, 16, 8, wmma::precision::tf32, wmma::row_major> bf[2];
        #pragma unroll
        for (int i = 0; i < 2; i++)
            wmma::load_matrix_sync(af[i], sq + (wm * 32 + i * 16) * HS + kk, HS);
        #pragma unroll
        for (int j = 0; j < 2; j++)
            wmma::load_matrix_sync(bf[j], sv + kk * HS + wn * 32 + j * 16, HS);
        #pragma unroll
        for (int i = 0; i < 2; i++)
            #pragma unroll
            for (int j = 0; j < 2; j++)
                wmma::mma_sync(acc[i][j], af[i], bf[j], acc[i][j]);
    }

    float* ob = out + (size_t)b * TT * HS;
    #pragma unroll
    for (int i = 0; i < 2; i++)
        #pragma unroll
        for (int j = 0; j < 2; j++)
            wmma::store_matrix_sync(ob + (wm * 32 + i * 16) * HS + wn * 32 + j * 16,
                                    acc[i][j], HS, wmma::mem_row_major);
}

// ---------------------------------------------------------------------------
extern "C" void kernel_launch(void* const* d_in, const int* in_sizes, int n_in,
                              void* d_out, int out_size)
{
    const float* x  = (const float*)d_in[0];
    const float* Wq = (const float*)d_in[1];
    const float* Wk = (const float*)d_in[2];
    const float* Wv = (const float*)d_in[3];
    float* out = (float*)d_out;

    const int smem2 = 3 * 128 * 128 * sizeof(float);      // 192 KB

    cudaFuncSetAttribute(qkv_rope_kernel, cudaFuncAttributeMaxDynamicSharedMemorySize, QKV_SMEM);
    cudaFuncSetAttribute(attn_kernel,     cudaFuncAttributeMaxDynamicSharedMemorySize, smem2);

    conv_w_kernel<<<96, 256>>>(Wq, Wk, Wv);

    qkv_rope_kernel<<<dim3(3, 128), 512, QKV_SMEM>>>(x);
    attn_kernel<<<NB, 512, smem2>>>(out);
}

// round 7
// speedup vs baseline: 2.9656x; 2.9656x over previous
#include <cuda_runtime.h>
#include <cuda_fp16.h>
#include <cstdint>
#include <mma.h>

using namespace nvcuda;

#define NEMBD 1024
#define TT 128
#define HS 128
#define NB 256

// Scratch (device globals; no allocations allowed).
__device__ __half g_qh[(size_t)NB * TT * HS];
__device__ __half g_kh[(size_t)NB * TT * HS];
__device__ __half g_vh[(size_t)NB * TT * HS];
__device__ __half g_xh[(size_t)NB * TT * NEMBD];   // x, RN-rounded to fp16
__device__ __half g_wh[(size_t)3 * NEMBD * HS];    // Wq|Wk|Wv, RN-rounded to fp16

// ---------------------------------------------------------------------------
// Pre-pass: RN-round fp32 -> fp16.
// ---------------------------------------------------------------------------
__global__ void conv_xh_kernel(const float* __restrict__ src)
{
    const int n4 = NB * TT * NEMBD / 4;         // 8388608 float4 tasks
    int stride = gridDim.x * blockDim.x;
    for (int i = blockIdx.x * blockDim.x + threadIdx.x; i < n4; i += stride) {
        float4 v = reinterpret_cast<const float4*>(src)[i];
        __half2 h0 = __floats2half2_rn(v.x, v.y);
        __half2 h1 = __floats2half2_rn(v.z, v.w);
        reinterpret_cast<__half2*>(g_xh)[i * 2 + 0] = h0;
        reinterpret_cast<__half2*>(g_xh)[i * 2 + 1] = h1;
    }
}

__global__ void conv_wh_kernel(const float* __restrict__ wq,
                               const float* __restrict__ wk,
                               const float* __restrict__ wv)
{
    const int n4 = NEMBD * HS / 4;              // per weight
    int stride = gridDim.x * blockDim.x;
    for (int i = blockIdx.x * blockDim.x + threadIdx.x; i < 3 * n4; i += stride) {
        int w = i / n4, j = i % n4;
        const float* src = (w == 0) ? wq : (w == 1) ? wk : wv;
        float4 v = reinterpret_cast<const float4*>(src)[j];
        reinterpret_cast<__half2*>(g_wh)[i * 2 + 0] = __floats2half2_rn(v.x, v.y);
        reinterpret_cast<__half2*>(g_wh)[i * 2 + 1] = __floats2half2_rn(v.z, v.w);
    }
}

// ---------------------------------------------------------------------------
// QKV GEMM + RoPE (fp16 HMMA). Grid (3 weights, 128 row-pairs). CTA tile:
// 256 rows x 128 cols, 256 threads / 8 warps (4x2), warp tile 64x64.
// 4-buffer cp.async pipeline, 3 deep, K chunks of 32.
// ---------------------------------------------------------------------------
static constexpr int AS_LD = 40;                       // halves (32 data + 8 pad)
static constexpr int BS_LD = 136;                      // halves (128 data + 8 pad)
static constexpr int A_HL  = 256 * AS_LD;              // 10240 halves
static constexpr int B_HL  = 32 * BS_LD;               // 4352 halves
static constexpr int ST_HL = A_HL + B_HL;              // 14592 halves = 29184 B
static constexpr int NBUF  = 4;
static constexpr int CS_LD = 132;                      // fp32 C tile ld
static constexpr int QKV_SMEM = (NBUF * ST_HL * 2 > 256 * CS_LD * 4)
                              ? NBUF * ST_HL * 2 : 256 * CS_LD * 4;  // 135168 B

__device__ __forceinline__ void cp_async16(uint32_t saddr, const void* gptr)
{
    asm volatile("cp.async.cg.shared.global [%0], [%1], 16;\n"
                 :: "r"(saddr), "l"(gptr));
}

__global__ void __launch_bounds__(256)
qkv_rope_kernel()
{
    extern __shared__ char smemc[];
    __half* smem = reinterpret_cast<__half*>(smemc);
    const int w    = blockIdx.x;          // 0=q 1=k 2=v
    const int b2   = blockIdx.y;          // rows b2*256 .. +255
    const int tid  = threadIdx.x;
    const int warp = tid >> 5;
    const int wm   = warp >> 1;           // 0..3 -> 64-row band
    const int wn   = warp & 1;            // 0..1 -> 64-col band

    const __half* xbase = g_xh + (size_t)b2 * 256 * NEMBD;
    const __half* wbase = g_wh + (size_t)w * NEMBD * HS;

    wmma::fragment<wmma::accumulator, 16, 16, 16, float> acc[4][4];
    #pragma unroll
    for (int i = 0; i < 4; i++)
        #pragma unroll
        for (int j = 0; j < 4; j++)
            wmma::fill_fragment(acc[i][j], 0.0f);

    auto load_stage = [&](int stage) {      // stage 0..31
        __half* As = smem + (stage & 3) * ST_HL;
        __half* Bs = As + A_HL;
        int k0 = stage * 32;
        // A: 256 rows x 32 halves = 4 chunks of 8 halves -> 1024 ops, 4/thread
        #pragma unroll
        for (int j = 0; j < 4; j++) {
            int idx = tid + j * 256;
            int r = idx >> 2, c = idx & 3;
            uint32_t sa = (uint32_t)__cvta_generic_to_shared(As + r * AS_LD + c * 8);
            cp_async16(sa, xbase + (size_t)r * NEMBD + k0 + c * 8);
        }
        // B: 32 rows x 128 halves = 16 chunks -> 512 ops, 2/thread
        #pragma unroll
        for (int j = 0; j < 2; j++) {
            int idx = tid + j * 256;
            int r = idx >> 4, c = idx & 15;
            uint32_t sa = (uint32_t)__cvta_generic_to_shared(Bs + r * BS_LD + c * 8);
            cp_async16(sa, wbase + (size_t)(k0 + r) * HS + c * 8);
        }
    };

    load_stage(0); asm volatile("cp.async.commit_group;\n");
    load_stage(1); asm volatile("cp.async.commit_group;\n");
    load_stage(2); asm volatile("cp.async.commit_group;\n");

    for (int it = 0; it < 32; ++it) {
        asm volatile("cp.async.wait_group 2;\n");
        __syncthreads();

        const __half* As = smem + (it & 3) * ST_HL;
        const __half* Bs = As + A_HL;

        #pragma unroll
        for (int kk = 0; kk < 32; kk += 16) {
            wmma::fragment<wmma::matrix_a, 16, 16, 16, __half, wmma::row_major> af[4];
            wmma::fragment<wmma::matrix_b, 16, 16, 16, __half, wmma::row_major> bf[4];
            #pragma unroll
            for (int i = 0; i < 4; i++)
                wmma::load_matrix_sync(af[i], As + (wm * 64 + i * 16) * AS_LD + kk, AS_LD);
            #pragma unroll
            for (int j = 0; j < 4; j++)
                wmma::load_matrix_sync(bf[j], Bs + kk * BS_LD + wn * 64 + j * 16, BS_LD);
            #pragma unroll
            for (int i = 0; i < 4; i++)
                #pragma unroll
                for (int j = 0; j < 4; j++)
                    wmma::mma_sync(acc[i][j], af[i], bf[j], acc[i][j]);
        }

        if (it + 3 < 32) load_stage(it + 3);
        asm volatile("cp.async.commit_group;\n");   // empty group keeps numbering
    }

    asm volatile("cp.async.wait_group 0;\n");
    __syncthreads();

    // Park C (256 x 128 fp32) in smem.
    float* Cs = reinterpret_cast<float*>(smemc);
    #pragma unroll
    for (int i = 0; i < 4; i++)
        #pragma unroll
        for (int j = 0; j < 4; j++)
            wmma::store_matrix_sync(Cs + (wm * 64 + i * 16) * CS_LD + wn * 64 + j * 16,
                                    acc[i][j], CS_LD, wmma::mem_row_major);
    __syncthreads();

    __half* outb = ((w == 0) ? g_qh : (w == 1) ? g_kh : g_vh) + (size_t)b2 * 256 * HS;
    const float qscale = (w == 0) ? 0.08838834764831845f : 1.0f;  // 1/sqrt(128)
    const float nlt = -logf(10000.0f) * (2.0f / 128.0f);

    for (int idx = tid; idx < 256 * 64; idx += 256) {   // pair index
        int r = idx >> 6;            // 0..255
        int p = idx & 63;
        float cr = Cs[r * CS_LD + 2 * p];
        float ci = Cs[r * CS_LD + 2 * p + 1];
        float o0, o1;
        if (w == 2) {
            o0 = cr; o1 = ci;
        } else {
            int t = r & 127;         // position within sequence
            float inv_freq = __expf(nlt * (float)p);
            float ang = (float)t * inv_freq;
            float s, c;
            sincosf(ang, &s, &c);
            o0 = (cr * c - ci * s) * qscale;
            o1 = (cr * s + ci * c) * qscale;
        }
        reinterpret_cast<__half2*>(outb)[r * 64 + p] = __floats2half2_rn(o0, o1);
    }
}

// ---------------------------------------------------------------------------
// Kernel 2: per-batch attention, fp16 MMA, fp32 S + softmax, fp16 P.
// 256 threads / 8 warps (4 row x 2 col), warp tile 32x64.
// ---------------------------------------------------------------------------
static constexpr int QK_LD = 136;      // halves
static constexpr int SS_LD = 132;      // floats
static constexpr int ATTN_SMEM = 3 * 128 * QK_LD * 2 + 128 * SS_LD * 4;  // 172032 B

__global__ void __launch_bounds__(256)
attn_kernel(float* __restrict__ out)
{
    extern __shared__ char smemc[];
    __half* sq = reinterpret_cast<__half*>(smemc);                 // [128][136] P later
    __half* sk = sq + 128 * QK_LD;
    __half* sv = sk + 128 * QK_LD;
    float*  sS = reinterpret_cast<float*>(smemc + 3 * 128 * QK_LD * 2);  // [128][132]

    const int b    = blockIdx.x;
    const int tid  = threadIdx.x;
    const int warp = tid >> 5;
    const int lane = tid & 31;
    const int wm   = warp >> 1;
    const int wn   = warp & 1;

    const __half* gq = g_qh + (size_t)b * TT * HS;
    const __half* gk = g_kh + (size_t)b * TT * HS;
    const __half* gv = g_vh + (size_t)b * TT * HS;

    // Load q,k,v tiles (16B chunks), 128 rows x 16 chunks each.
    for (int i = tid; i < 128 * 16; i += 256) {
        int r = i >> 4, c = i & 15;
        uint4 a = reinterpret_cast<const uint4*>(gq + (size_t)r * HS)[c];
        uint4 kk = reinterpret_cast<const uint4*>(gk + (size_t)r * HS)[c];
        uint4 d = reinterpret_cast<const uint4*>(gv + (size_t)r * HS)[c];
        reinterpret_cast<uint4*>(sq + r * QK_LD)[c] = a;
        reinterpret_cast<uint4*>(sk + r * QK_LD)[c] = kk;
        reinterpret_cast<uint4*>(sv + r * QK_LD)[c] = d;
    }
    __syncthreads();

    // S = q @ k^T  (k col-major view)
    wmma::fragment<wmma::accumulator, 16, 16, 16, float> acc[2][4];
    #pragma unroll
    for (int i = 0; i < 2; i++)
        #pragma unroll
        for (int j = 0; j < 4; j++)
            wmma::fill_fragment(acc[i][j], 0.0f);

    #pragma unroll
    for (int kk = 0; kk < HS; kk += 16) {
        wmma::fragment<wmma::matrix_a, 16, 16, 16, __half, wmma::row_major> af[2];
        wmma::fragment<wmma::matrix_b, 16, 16, 16, __half, wmma::col_major> bf[4];
        #pragma unroll
        for (int i = 0; i < 2; i++)
            wmma::load_matrix_sync(af[i], sq + (wm * 32 + i * 16) * QK_LD + kk, QK_LD);
        #pragma unroll
        for (int j = 0; j < 4; j++)
            wmma::load_matrix_sync(bf[j], sk + (wn * 64 + j * 16) * QK_LD + kk, QK_LD);
        #pragma unroll
        for (int i = 0; i < 2; i++)
            #pragma unroll
            for (int j = 0; j < 4; j++)
                wmma::mma_sync(acc[i][j], af[i], bf[j], acc[i][j]);
    }

    #pragma unroll
    for (int i = 0; i < 2; i++)
        #pragma unroll
        for (int j = 0; j < 4; j++)
            wmma::store_matrix_sync(sS + (wm * 32 + i * 16) * SS_LD + wn * 64 + j * 16,
                                    acc[i][j], SS_LD, wmma::mem_row_major);
    __syncthreads();

    // Warp-parallel causal softmax; each warp handles 16 rows; P -> sq (fp16).
    #pragma unroll 1
    for (int rr = 0; rr < 16; rr++) {
        const int t = warp * 16 + rr;
        float4 v4 = reinterpret_cast<float4*>(sS + t * SS_LD)[lane];
        const int c0 = lane * 4;

        float m = -1e30f;
        if (c0 + 0 <= t) m = fmaxf(m, v4.x);
        if (c0 + 1 <= t) m = fmaxf(m, v4.y);
        if (c0 + 2 <= t) m = fmaxf(m, v4.z);
        if (c0 + 3 <= t) m = fmaxf(m, v4.w);
        #pragma unroll
        for (int off = 16; off > 0; off >>= 1)
            m = fmaxf(m, __shfl_xor_sync(0xffffffffu, m, off));

        float e0 = (c0 + 0 <= t) ? __expf(v4.x - m) : 0.0f;
        float e1 = (c0 + 1 <= t) ? __expf(v4.y - m) : 0.0f;
        float e2 = (c0 + 2 <= t) ? __expf(v4.z - m) : 0.0f;
        float e3 = (c0 + 3 <= t) ? __expf(v4.w - m) : 0.0f;
        float s = e0 + e1 + e2 + e3;
        #pragma unroll
        for (int off = 16; off > 0; off >>= 1)
            s += __shfl_xor_sync(0xffffffffu, s, off);

        float inv = 1.0f / s;
        __half2* prow = reinterpret_cast<__half2*>(sq + t * QK_LD);
        prow[lane * 2 + 0] = __floats2half2_rn(e0 * inv, e1 * inv);
        prow[lane * 2 + 1] = __floats2half2_rn(e2 * inv, e3 * inv);
    }
    __syncthreads();

    // O = P @ v
    #pragma unroll
    for (int i = 0; i < 2; i++)
        #pragma unroll
        for (int j = 0; j < 4; j++)
            wmma::fill_fragment(acc[i][j], 0.0f);

    #pragma unroll
    for (int kk = 0; kk < TT; kk += 16) {
        wmma::fragment<wmma::matrix_a, 16, 16, 16, __half, wmma::row_major> af[2];
        wmma::fragment<wmma::matrix_b, 16, 16, 16, __half, wmma::row_major> bf[4];
        #pragma unroll
        for (int i = 0; i < 2; i++)
            wmma::load_matrix_sync(af[i], sq + (wm * 32 + i * 16) * QK_LD + kk, QK_LD);
        #pragma unroll
        for (int j = 0; j < 4; j++)
            wmma::load_matrix_sync(bf[j], sv + kk * QK_LD + wn * 64 + j * 16, QK_LD);
        #pragma unroll
        for (int i = 0; i < 2; i++)
            #pragma unroll
            for (int j = 0; j < 4; j++)
                wmma::mma_sync(acc[i][j], af[i], bf[j], acc[i][j]);
    }

    float* ob = out + (size_t)b * TT * HS;
    #pragma unroll
    for (int i = 0; i < 2; i++)
        #pragma unroll
        for (int j = 0; j < 4; j++)
            wmma::store_matrix_sync(ob + (wm * 32 + i * 16) * HS + wn * 64 + j * 16,
                                    acc[i][j], HS, wmma::mem_row_major);
}

// ---------------------------------------------------------------------------
extern "C" void kernel_launch(void* const* d_in, const int* in_sizes, int n_in,
                              void* d_out, int out_size)
{
    const float* x  = (const float*)d_in[0];
    const float* Wq = (const float*)d_in[1];
    const float* Wk = (const float*)d_in[2];
    const float* Wv = (const float*)d_in[3];
    float* out = (float*)d_out;

    cudaFuncSetAttribute(qkv_rope_kernel, cudaFuncAttributeMaxDynamicSharedMemorySize, QKV_SMEM);
    cudaFuncSetAttribute(attn_kernel,     cudaFuncAttributeMaxDynamicSharedMemorySize, ATTN_SMEM);

    conv_xh_kernel<<<1024, 256>>>(x);
    conv_wh_kernel<<<96, 256>>>(Wq, Wk, Wv);

    qkv_rope_kernel<<<dim3(3, 128), 256, QKV_SMEM>>>();
    attn_kernel<<<NB, 256, ATTN_SMEM>>>(out);
}

// round 8
// speedup vs baseline: 3.3533x; 1.1307x over previous
#include <cuda_runtime.h>
#include <cuda_fp16.h>
#include <cstdint>
#include <mma.h>

using namespace nvcuda;

#define NEMBD 1024
#define TT 128
#define HS 128
#define NB 256

// Scratch (device globals; no allocations allowed).
__device__ __half g_qh[(size_t)NB * TT * HS];
__device__ __half g_kh[(size_t)NB * TT * HS];
__device__ __half g_vh[(size_t)NB * TT * HS];
__device__ __half g_wh[(size_t)3 * NEMBD * HS];    // Wq|Wk|Wv, RN-rounded to fp16

// ---------------------------------------------------------------------------
// Pre-pass: RN-round W fp32 -> fp16 (x converted in-smem inside the GEMM).
// ---------------------------------------------------------------------------
__global__ void conv_wh_kernel(const float* __restrict__ wq,
                               const float* __restrict__ wk,
                               const float* __restrict__ wv)
{
    const int n4 = NEMBD * HS / 4;              // per weight
    int stride = gridDim.x * blockDim.x;
    for (int i = blockIdx.x * blockDim.x + threadIdx.x; i < 3 * n4; i += stride) {
        int w = i / n4, j = i % n4;
        const float* src = (w == 0) ? wq : (w == 1) ? wk : wv;
        float4 v = reinterpret_cast<const float4*>(src)[j];
        reinterpret_cast<__half2*>(g_wh)[i * 2 + 0] = __floats2half2_rn(v.x, v.y);
        reinterpret_cast<__half2*>(g_wh)[i * 2 + 1] = __floats2half2_rn(v.z, v.w);
    }
}

// ---------------------------------------------------------------------------
// Fused QKV GEMM + RoPE (fp16 HMMA). Grid: 256 CTAs (one batch each).
// CTA tile: 128 rows x 384 cols (q|k|v). 512 threads / 16 warps (4x4),
// warp tile 32x96. 4-buffer cp.async pipeline, 3 deep, K chunks of 32.
// x loaded raw fp32 and converted to fp16 in-smem per stage.
// ---------------------------------------------------------------------------
static constexpr int A32_LD = 36;                      // floats (32 + 4 pad)
static constexpr int AH_LD  = 40;                      // halves (32 + 8 pad)
static constexpr int BH_LD  = 392;                     // halves (384 + 8 pad)
static constexpr int A32_B  = 128 * A32_LD * 4;        // 18432 B
static constexpr int AH_B   = 128 * AH_LD * 2;         // 10240 B
static constexpr int BH_B   = 32 * BH_LD * 2;          // 25088 B
static constexpr int STG_B  = A32_B + AH_B + BH_B;     // 53760 B
static constexpr int NBUF   = 4;
static constexpr int CS_LD  = 392;                     // floats (384 + 8 pad)
static constexpr int QKV_SMEM = NBUF * STG_B;          // 215040 B (Cs 200704 fits)

__device__ __forceinline__ void cp_async16(uint32_t saddr, const void* gptr)
{
    asm volatile("cp.async.cg.shared.global [%0], [%1], 16;\n"
                 :: "r"(saddr), "l"(gptr));
}

__global__ void __launch_bounds__(512)
qkv_fused_kernel(const float* __restrict__ x)
{
    extern __shared__ char smemc[];
    const int b    = blockIdx.x;          // batch
    const int tid  = threadIdx.x;
    const int warp = tid >> 5;
    const int wm   = warp >> 2;           // 0..3 -> 32-row band
    const int wn   = warp & 3;            // 0..3 -> 96-col band

    const float* xbase = x + (size_t)b * TT * NEMBD;

    wmma::fragment<wmma::accumulator, 16, 16, 16, float> acc[2][6];
    #pragma unroll
    for (int i = 0; i < 2; i++)
        #pragma unroll
        for (int j = 0; j < 6; j++)
            wmma::fill_fragment(acc[i][j], 0.0f);

    auto load_stage = [&](int stage) {      // stage 0..31
        char* st = smemc + (stage & 3) * STG_B;
        float*  As32 = reinterpret_cast<float*>(st);
        __half* Bs   = reinterpret_cast<__half*>(st + A32_B + AH_B);
        int k0 = stage * 32;
        // A: 128 rows x 8 float4 chunks = 1024 ops, 2/thread (raw fp32 x)
        #pragma unroll
        for (int j = 0; j < 2; j++) {
            int idx = tid + j * 512;
            int r = idx >> 3, c4 = idx & 7;
            uint32_t sa = (uint32_t)__cvta_generic_to_shared(As32 + r * A32_LD + c4 * 4);
            cp_async16(sa, xbase + (size_t)r * NEMBD + k0 + c4 * 4);
        }
        // B: 32 rows x 48 8-half chunks = 1536 ops, 3/thread
        #pragma unroll
        for (int j = 0; j < 3; j++) {
            int idx = tid + j * 512;
            int r = idx / 48, c = idx % 48;
            int w = c >> 4;                   // weight section
            int cc = (c & 15) * 8;            // half col within section
            uint32_t sa = (uint32_t)__cvta_generic_to_shared(Bs + r * BH_LD + c * 8);
            cp_async16(sa, g_wh + (size_t)w * NEMBD * HS + (size_t)(k0 + r) * HS + cc);
        }
    };

    load_stage(0); asm volatile("cp.async.commit_group;\n");
    load_stage(1); asm volatile("cp.async.commit_group;\n");
    load_stage(2); asm volatile("cp.async.commit_group;\n");

    for (int it = 0; it < 32; ++it) {
        asm volatile("cp.async.wait_group 2;\n");
        __syncthreads();

        char* st = smemc + (it & 3) * STG_B;
        float*  As32 = reinterpret_cast<float*>(st);
        __half* Ah   = reinterpret_cast<__half*>(st + A32_B);
        __half* Bs   = reinterpret_cast<__half*>(st + A32_B + AH_B);

        // Convert this stage's A: fp32 -> fp16 (4096 elems, 8/thread).
        #pragma unroll
        for (int j = 0; j < 8; j++) {
            int idx = tid + j * 512;
            int r = idx >> 5, c = idx & 31;
            Ah[r * AH_LD + c] = __float2half_rn(As32[r * A32_LD + c]);
        }
        __syncthreads();

        #pragma unroll
        for (int kk = 0; kk < 32; kk += 16) {
            wmma::fragment<wmma::matrix_a, 16, 16, 16, __half, wmma::row_major> af[2];
            wmma::fragment<wmma::matrix_b, 16, 16, 16, __half, wmma::row_major> bf[6];
            #pragma unroll
            for (int i = 0; i < 2; i++)
                wmma::load_matrix_sync(af[i], Ah + (wm * 32 + i * 16) * AH_LD + kk, AH_LD);
            #pragma unroll
            for (int j = 0; j < 6; j++)
                wmma::load_matrix_sync(bf[j], Bs + kk * BH_LD + wn * 96 + j * 16, BH_LD);
            #pragma unroll
            for (int i = 0; i < 2; i++)
                #pragma unroll
                for (int j = 0; j < 6; j++)
                    wmma::mma_sync(acc[i][j], af[i], bf[j], acc[i][j]);
        }

        if (it + 3 < 32) load_stage(it + 3);
        asm volatile("cp.async.commit_group;\n");   // empty group keeps numbering
    }

    asm volatile("cp.async.wait_group 0;\n");
    __syncthreads();

    // Park C (128 x 384 fp32) in smem.
    float* Cs = reinterpret_cast<float*>(smemc);
    #pragma unroll
    for (int i = 0; i < 2; i++)
        #pragma unroll
        for (int j = 0; j < 6; j++)
            wmma::store_matrix_sync(Cs + (wm * 32 + i * 16) * CS_LD + wn * 96 + j * 16,
                                    acc[i][j], CS_LD, wmma::mem_row_major);
    __syncthreads();

    // Epilogue: 128 rows x 192 pairs. RoPE for q/k sections, copy for v.
    const float nlt = -logf(10000.0f) * (2.0f / 128.0f);
    for (int idx = tid; idx < 128 * 192; idx += 512) {
        int r  = idx / 192;          // row == position t
        int pp = idx % 192;
        int w  = pp >> 6;            // 0=q 1=k 2=v
        int p  = pp & 63;            // pair within section
        float cr = Cs[r * CS_LD + w * 128 + 2 * p];
        float ci = Cs[r * CS_LD + w * 128 + 2 * p + 1];
        float o0, o1;
        if (w == 2) {
            o0 = cr; o1 = ci;
        } else {
            float inv_freq = __expf(nlt * (float)p);
            float ang = (float)r * inv_freq;
            float s, c;
            sincosf(ang, &s, &c);
            float qs = (w == 0) ? 0.08838834764831845f : 1.0f;  // 1/sqrt(128)
            o0 = (cr * c - ci * s) * qs;
            o1 = (cr * s + ci * c) * qs;
        }
        __half* outb = ((w == 0) ? g_qh : (w == 1) ? g_kh : g_vh) + (size_t)b * TT * HS;
        reinterpret_cast<__half2*>(outb)[r * 64 + p] = __floats2half2_rn(o0, o1);
    }
}

// ---------------------------------------------------------------------------
// Kernel 2: per-batch attention, fp16 MMA, fp32 S + softmax, fp16 P.
// smem = 3 fp16 tiles only (104.4 KB -> 2 CTAs/SM). S (fp32) overlays the
// dead q+k regions after QK^T; P overwrites S in place (row stride 264 halves).
// 256 threads / 8 warps (4 row x 2 col), warp tile 32x64.
// ---------------------------------------------------------------------------
static constexpr int QK_LD = 136;      // halves
static constexpr int SS_LD = 132;      // floats (row = 528 B = 264 halves)
static constexpr int SP_LD = 264;      // halves (P view of the S region)
static constexpr int ATTN_SMEM = 3 * 128 * QK_LD * 2;   // 104448 B

__global__ void __launch_bounds__(256)
attn_kernel(float* __restrict__ out)
{
    extern __shared__ char smemc[];
    __half* sq = reinterpret_cast<__half*>(smemc);
    __half* sk = sq + 128 * QK_LD;
    __half* sv = sk + 128 * QK_LD;
    float*  sS = reinterpret_cast<float*>(smemc);   // overlays sq+sk (67584 <= 69632)
    __half* sp = reinterpret_cast<__half*>(smemc);  // P, row stride SP_LD

    const int b    = blockIdx.x;
    const int tid  = threadIdx.x;
    const int warp = tid >> 5;
    const int lane = tid & 31;
    const int wm   = warp >> 1;
    const int wn   = warp & 1;

    const __half* gq = g_qh + (size_t)b * TT * HS;
    const __half* gk = g_kh + (size_t)b * TT * HS;
    const __half* gv = g_vh + (size_t)b * TT * HS;

    for (int i = tid; i < 128 * 16; i += 256) {
        int r = i >> 4, c = i & 15;
        uint4 a  = reinterpret_cast<const uint4*>(gq + (size_t)r * HS)[c];
        uint4 kk = reinterpret_cast<const uint4*>(gk + (size_t)r * HS)[c];
        uint4 d  = reinterpret_cast<const uint4*>(gv + (size_t)r * HS)[c];
        reinterpret_cast<uint4*>(sq + r * QK_LD)[c] = a;
        reinterpret_cast<uint4*>(sk + r * QK_LD)[c] = kk;
        reinterpret_cast<uint4*>(sv + r * QK_LD)[c] = d;
    }
    __syncthreads();

    // S = q @ k^T  (k col-major view)
    wmma::fragment<wmma::accumulator, 16, 16, 16, float> acc[2][4];
    #pragma unroll
    for (int i = 0; i < 2; i++)
        #pragma unroll
        for (int j = 0; j < 4; j++)
            wmma::fill_fragment(acc[i][j], 0.0f);

    #pragma unroll
    for (int kk = 0; kk < HS; kk += 16) {
        wmma::fragment<wmma::matrix_a, 16, 16, 16, __half, wmma::row_major> af[2];
        wmma::fragment<wmma::matrix_b, 16, 16, 16, __half, wmma::col_major> bf[4];
        #pragma unroll
        for (int i = 0; i < 2; i++)
            wmma::load_matrix_sync(af[i], sq + (wm * 32 + i * 16) * QK_LD + kk, QK_LD);
        #pragma unroll
        for (int j = 0; j < 4; j++)
            wmma::load_matrix_sync(bf[j], sk + (wn * 64 + j * 16) * QK_LD + kk, QK_LD);
        #pragma unroll
        for (int i = 0; i < 2; i++)
            #pragma unroll
            for (int j = 0; j < 4; j++)
                wmma::mma_sync(acc[i][j], af[i], bf[j], acc[i][j]);
    }
    __syncthreads();   // all reads of q,k done before S overwrites them

    #pragma unroll
    for (int i = 0; i < 2; i++)
        #pragma unroll
        for (int j = 0; j < 4; j++)
            wmma::store_matrix_sync(sS + (wm * 32 + i * 16) * SS_LD + wn * 64 + j * 16,
                                    acc[i][j], SS_LD, wmma::mem_row_major);
    __syncthreads();

    // Warp-parallel causal softmax; each warp handles 16 rows.
    // P (fp16) overwrites S row-in-place: row t -> halves at sp + t*SP_LD.
    #pragma unroll 1
    for (int rr = 0; rr < 16; rr++) {
        const int t = warp * 16 + rr;
        float4 v4 = reinterpret_cast<float4*>(sS + t * SS_LD)[lane];
        const int c0 = lane * 4;

        float m = -1e30f;
        if (c0 + 0 <= t) m = fmaxf(m, v4.x);
        if (c0 + 1 <= t) m = fmaxf(m, v4.y);
        if (c0 + 2 <= t) m = fmaxf(m, v4.z);
        if (c0 + 3 <= t) m = fmaxf(m, v4.w);
        #pragma unroll
        for (int off = 16; off > 0; off >>= 1)
            m = fmaxf(m, __shfl_xor_sync(0xffffffffu, m, off));

        float e0 = (c0 + 0 <= t) ? __expf(v4.x - m) : 0.0f;
        float e1 = (c0 + 1 <= t) ? __expf(v4.y - m) : 0.0f;
        float e2 = (c0 + 2 <= t) ? __expf(v4.z - m) : 0.0f;
        float e3 = (c0 + 3 <= t) ? __expf(v4.w - m) : 0.0f;
        float s = e0 + e1 + e2 + e3;
        #pragma unroll
        for (int off = 16; off > 0; off >>= 1)
            s += __shfl_xor_sync(0xffffffffu, s, off);

        // shfl reductions converge the warp: every lane's loads completed
        // before any lane reaches the stores below (same-row overwrite safe).
        float inv = 1.0f / s;
        __half2* prow = reinterpret_cast<__half2*>(sp + t * SP_LD);
        prow[lane * 2 + 0] = __floats2half2_rn(e0 * inv, e1 * inv);
        prow[lane * 2 + 1] = __floats2half2_rn(e2 * inv, e3 * inv);
    }
    __syncthreads();

    // O = P @ v
    #pragma unroll
    for (int i = 0; i < 2; i++)
        #pragma unroll
        for (int j = 0; j < 4; j++)
            wmma::fill_fragment(acc[i][j], 0.0f);

    #pragma unroll
    for (int kk = 0; kk < TT; kk += 16) {
        wmma::fragment<wmma::matrix_a, 16, 16, 16, __half, wmma::row_major> af[2];
        wmma::fragment<wmma::matrix_b, 16, 16, 16, __half, wmma::row_major> bf[4];
        #pragma unroll
        for (int i = 0; i < 2; i++)
            wmma::load_matrix_sync(af[i], sp + (wm * 32 + i * 16) * SP_LD + kk, SP_LD);
        #pragma unroll
        for (int j = 0; j < 4; j++)
            wmma::load_matrix_sync(bf[j], sv + kk * QK_LD + wn * 64 + j * 16, QK_LD);
        #pragma unroll
        for (int i = 0; i < 2; i++)
            #pragma unroll
            for (int j = 0; j < 4; j++)
                wmma::mma_sync(acc[i][j], af[i], bf[j], acc[i][j]);
    }

    float* ob = out + (size_t)b * TT * HS;
    #pragma unroll
    for (int i = 0; i < 2; i++)
        #pragma unroll
        for (int j = 0; j < 4; j++)
            wmma::store_matrix_sync(ob + (wm * 32 + i * 16) * HS + wn * 64 + j * 16,
                                    acc[i][j], HS, wmma::mem_row_major);
}

// ---------------------------------------------------------------------------
extern "C" void kernel_launch(void* const* d_in, const int* in_sizes, int n_in,
                              void* d_out, int out_size)
{
    const float* x  = (const float*)d_in[0];
    const float* Wq = (const float*)d_in[1];
    const float* Wk = (const float*)d_in[2];
    const float* Wv = (const float*)d_in[3];
    float* out = (float*)d_out;

    cudaFuncSetAttribute(qkv_fused_kernel, cudaFuncAttributeMaxDynamicSharedMemorySize, QKV_SMEM);
    cudaFuncSetAttribute(attn_kernel,      cudaFuncAttributeMaxDynamicSharedMemorySize, ATTN_SMEM);

    conv_wh_kernel<<<96, 256>>>(Wq, Wk, Wv);

    qkv_fused_kernel<<<NB, 512, QKV_SMEM>>>(x);
    attn_kernel<<<NB, 256, ATTN_SMEM>>>(out);
}

// round 9
// speedup vs baseline: 3.6139x; 1.0777x over previous
#include <cuda_runtime.h>
#include <cuda_fp16.h>
#include <cstdint>
#include <mma.h>

using namespace nvcuda;

#define NEMBD 1024
#define TT 128
#define HS 128
#define NB 256

// W pre-converted to fp16 (device global; no allocations allowed).
__device__ __half g_wh[(size_t)3 * NEMBD * HS];    // Wq|Wk|Wv, RN fp16

// ---------------------------------------------------------------------------
// Pre-pass: RN-round W fp32 -> fp16.
// ---------------------------------------------------------------------------
__global__ void conv_wh_kernel(const float* __restrict__ wq,
                               const float* __restrict__ wk,
                               const float* __restrict__ wv)
{
    const int n4 = NEMBD * HS / 4;              // per weight
    int stride = gridDim.x * blockDim.x;
    for (int i = blockIdx.x * blockDim.x + threadIdx.x; i < 3 * n4; i += stride) {
        int w = i / n4, j = i % n4;
        const float* src = (w == 0) ? wq : (w == 1) ? wk : wv;
        float4 v = reinterpret_cast<const float4*>(src)[j];
        reinterpret_cast<__half2*>(g_wh)[i * 2 + 0] = __floats2half2_rn(v.x, v.y);
        reinterpret_cast<__half2*>(g_wh)[i * 2 + 1] = __floats2half2_rn(v.z, v.w);
    }
}

// ---------------------------------------------------------------------------
// Fused kernel: per-batch QKV GEMM (fp16 HMMA, cp.async pipeline) + RoPE
// + causal attention. Grid: 256 CTAs, 512 threads / 16 warps.
//
// Phase 1 (GEMM): CTA tile 128 x 384 (q|k|v), warp grid 4x4, warp tile 32x96.
//   4-buffer / 3-deep cp.async pipeline over K chunks of 32; x loaded raw
//   fp32 and converted fp16 in-smem per stage.
// Phase 1 epilogue: per 128-col section, stage C (fp32) -> RoPE -> fp16 tile.
// Phase 2 (attn): S = qk^T (fp32, staged in the scratch region), warp-parallel
//   causal softmax, P fp16 in place, O = P @ v -> gmem.
// ---------------------------------------------------------------------------
static constexpr int A32_LD = 36;                      // floats (32 + 4 pad)
static constexpr int AH_LD  = 40;                      // halves (32 + 8 pad)
static constexpr int BH_LD  = 392;                     // halves (384 + 8 pad)
static constexpr int A32_B  = 128 * A32_LD * 4;        // 18432 B
static constexpr int AH_B   = 128 * AH_LD * 2;         // 10240 B
static constexpr int BH_B   = 32 * BH_LD * 2;          // 25088 B
static constexpr int STG_B  = A32_B + AH_B + BH_B;     // 53760 B
static constexpr int NBUF   = 4;
static constexpr int FUSED_SMEM = NBUF * STG_B;        // 215040 B

// Post-mainloop layout (within the same allocation):
static constexpr int SC_LD   = 132;                    // staging C / S, floats
static constexpr int SC_B    = 128 * SC_LD * 4;        // 67584 B
static constexpr int QK_LD   = 136;                    // fp16 tile ld (halves)
static constexpr int TILE_B  = 128 * QK_LD * 2;        // 34816 B
static constexpr int SQ_OFF  = SC_B;                   // 67584
static constexpr int SK_OFF  = SQ_OFF + TILE_B;        // 102400
static constexpr int SV_OFF  = SK_OFF + TILE_B;        // 137216  (end 172032)
static constexpr int SP_LD   = 264;                    // P halves ld (=132 floats)

__device__ __forceinline__ void cp_async16(uint32_t saddr, const void* gptr)
{
    asm volatile("cp.async.cg.shared.global [%0], [%1], 16;\n"
                 :: "r"(saddr), "l"(gptr));
}

__global__ void __launch_bounds__(512)
fused_head_kernel(const float* __restrict__ x, float* __restrict__ out)
{
    extern __shared__ char smemc[];
    const int b    = blockIdx.x;          // batch
    const int tid  = threadIdx.x;
    const int warp = tid >> 5;
    const int lane = tid & 31;
    const int wm   = warp >> 2;           // 0..3 -> 32-row band
    const int wn   = warp & 3;            // 0..3 -> 96-col band (phase 1)

    const float* xbase = x + (size_t)b * TT * NEMBD;

    // ============================ Phase 1: QKV GEMM ========================
    {
        wmma::fragment<wmma::accumulator, 16, 16, 16, float> acc[2][6];
        #pragma unroll
        for (int i = 0; i < 2; i++)
            #pragma unroll
            for (int j = 0; j < 6; j++)
                wmma::fill_fragment(acc[i][j], 0.0f);

        auto load_stage = [&](int stage) {      // stage 0..31
            char* st = smemc + (stage & 3) * STG_B;
            float*  As32 = reinterpret_cast<float*>(st);
            __half* Bs   = reinterpret_cast<__half*>(st + A32_B + AH_B);
            int k0 = stage * 32;
            #pragma unroll
            for (int j = 0; j < 2; j++) {       // A: 1024 float4 ops
                int idx = tid + j * 512;
                int r = idx >> 3, c4 = idx & 7;
                uint32_t sa = (uint32_t)__cvta_generic_to_shared(As32 + r * A32_LD + c4 * 4);
                cp_async16(sa, xbase + (size_t)r * NEMBD + k0 + c4 * 4);
            }
            #pragma unroll
            for (int j = 0; j < 3; j++) {       // B: 1536 8-half ops
                int idx = tid + j * 512;
                int r = idx / 48, c = idx % 48;
                int w = c >> 4;
                int cc = (c & 15) * 8;
                uint32_t sa = (uint32_t)__cvta_generic_to_shared(Bs + r * BH_LD + c * 8);
                cp_async16(sa, g_wh + (size_t)w * NEMBD * HS + (size_t)(k0 + r) * HS + cc);
            }
        };

        load_stage(0); asm volatile("cp.async.commit_group;\n");
        load_stage(1); asm volatile("cp.async.commit_group;\n");
        load_stage(2); asm volatile("cp.async.commit_group;\n");

        for (int it = 0; it < 32; ++it) {
            asm volatile("cp.async.wait_group 2;\n");
            __syncthreads();

            char* st = smemc + (it & 3) * STG_B;
            float*  As32 = reinterpret_cast<float*>(st);
            __half* Ah   = reinterpret_cast<__half*>(st + A32_B);
            __half* Bs   = reinterpret_cast<__half*>(st + A32_B + AH_B);

            #pragma unroll
            for (int j = 0; j < 8; j++) {       // fp32 -> fp16 (4096 elems)
                int idx = tid + j * 512;
                int r = idx >> 5, c = idx & 31;
                Ah[r * AH_LD + c] = __float2half_rn(As32[r * A32_LD + c]);
            }
            __syncthreads();

            #pragma unroll
            for (int kk = 0; kk < 32; kk += 16) {
                wmma::fragment<wmma::matrix_a, 16, 16, 16, __half, wmma::row_major> af[2];
                wmma::fragment<wmma::matrix_b, 16, 16, 16, __half, wmma::row_major> bf[6];
                #pragma unroll
                for (int i = 0; i < 2; i++)
                    wmma::load_matrix_sync(af[i], Ah + (wm * 32 + i * 16) * AH_LD + kk, AH_LD);
                #pragma unroll
                for (int j = 0; j < 6; j++)
                    wmma::load_matrix_sync(bf[j], Bs + kk * BH_LD + wn * 96 + j * 16, BH_LD);
                #pragma unroll
                for (int i = 0; i < 2; i++)
                    #pragma unroll
                    for (int j = 0; j < 6; j++)
                        wmma::mma_sync(acc[i][j], af[i], bf[j], acc[i][j]);
            }

            if (it + 3 < 32) load_stage(it + 3);
            asm volatile("cp.async.commit_group;\n");
        }

        asm volatile("cp.async.wait_group 0;\n");
        __syncthreads();

        // ---- Epilogue: per 128-col section, stage C -> RoPE -> fp16 tile --
        float* stage = reinterpret_cast<float*>(smemc);               // [128][132]
        const float nlt = -logf(10000.0f) * (2.0f / 128.0f);

        #pragma unroll
        for (int w = 0; w < 3; w++) {
            // Store this section's fragments (global cols [w*128, w*128+128)).
            #pragma unroll
            for (int i = 0; i < 2; i++)
                #pragma unroll
                for (int j = 0; j < 6; j++) {
                    int colg = wn * 96 + j * 16;
                    if (colg >= w * 128 && colg < w * 128 + 128)
                        wmma::store_matrix_sync(
                            stage + (wm * 32 + i * 16) * SC_LD + (colg - w * 128),
                            acc[i][j], SC_LD, wmma::mem_row_major);
                }
            __syncthreads();

            __half* tile = reinterpret_cast<__half*>(
                smemc + (w == 0 ? SQ_OFF : w == 1 ? SK_OFF : SV_OFF));
            const float qs = (w == 0) ? 0.08838834764831845f : 1.0f;  // 1/sqrt(128)

            for (int idx = tid; idx < 128 * 64; idx += 512) {   // (row, pair)
                int r = idx >> 6;
                int p = idx & 63;
                float cr = stage[r * SC_LD + 2 * p];
                float ci = stage[r * SC_LD + 2 * p + 1];
                float o0, o1;
                if (w == 2) {
                    o0 = cr; o1 = ci;
                } else {
                    float inv_freq = __expf(nlt * (float)p);
                    float ang = (float)r * inv_freq;
                    float s, c;
                    sincosf(ang, &s, &c);
                    o0 = (cr * c - ci * s) * qs;
                    o1 = (cr * s + ci * c) * qs;
                }
                reinterpret_cast<__half2*>(tile + r * QK_LD)[p] = __floats2half2_rn(o0, o1);
            }
            __syncthreads();
        }
    }

    // ============================ Phase 2: attention ========================
    {
        __half* sq = reinterpret_cast<__half*>(smemc + SQ_OFF);
        __half* sk = reinterpret_cast<__half*>(smemc + SK_OFF);
        __half* sv = reinterpret_cast<__half*>(smemc + SV_OFF);
        float*  sS = reinterpret_cast<float*>(smemc);        // [128][132]
        __half* sp = reinterpret_cast<__half*>(smemc);       // P view, ld 264

        const int wm2 = warp >> 2;   // 0..3 -> 32-row band
        const int wn2 = warp & 3;    // 0..3 -> 32-col band

        // S = q @ k^T
        wmma::fragment<wmma::accumulator, 16, 16, 16, float> acc[2][2];
        #pragma unroll
        for (int i = 0; i < 2; i++)
            #pragma unroll
            for (int j = 0; j < 2; j++)
                wmma::fill_fragment(acc[i][j], 0.0f);

        #pragma unroll
        for (int kk = 0; kk < HS; kk += 16) {
            wmma::fragment<wmma::matrix_a, 16, 16, 16, __half, wmma::row_major> af[2];
            wmma::fragment<wmma::matrix_b, 16, 16, 16, __half, wmma::col_major> bf[2];
            #pragma unroll
            for (int i = 0; i < 2; i++)
                wmma::load_matrix_sync(af[i], sq + (wm2 * 32 + i * 16) * QK_LD + kk, QK_LD);
            #pragma unroll
            for (int j = 0; j < 2; j++)
                wmma::load_matrix_sync(bf[j], sk + (wn2 * 32 + j * 16) * QK_LD + kk, QK_LD);
            #pragma unroll
            for (int i = 0; i < 2; i++)
                #pragma unroll
                for (int j = 0; j < 2; j++)
                    wmma::mma_sync(acc[i][j], af[i], bf[j], acc[i][j]);
        }

        #pragma unroll
        for (int i = 0; i < 2; i++)
            #pragma unroll
            for (int j = 0; j < 2; j++)
                wmma::store_matrix_sync(sS + (wm2 * 32 + i * 16) * SC_LD + wn2 * 32 + j * 16,
                                        acc[i][j], SC_LD, wmma::mem_row_major);
        __syncthreads();

        // Warp-parallel causal softmax: each warp handles 8 rows; P in place.
        #pragma unroll 1
        for (int rr = 0; rr < 8; rr++) {
            const int t = warp * 8 + rr;
            float4 v4 = reinterpret_cast<float4*>(sS + t * SC_LD)[lane];
            const int c0 = lane * 4;

            float m = -1e30f;
            if (c0 + 0 <= t) m = fmaxf(m, v4.x);
            if (c0 + 1 <= t) m = fmaxf(m, v4.y);
            if (c0 + 2 <= t) m = fmaxf(m, v4.z);
            if (c0 + 3 <= t) m = fmaxf(m, v4.w);
            #pragma unroll
            for (int off = 16; off > 0; off >>= 1)
                m = fmaxf(m, __shfl_xor_sync(0xffffffffu, m, off));

            float e0 = (c0 + 0 <= t) ? __expf(v4.x - m) : 0.0f;
            float e1 = (c0 + 1 <= t) ? __expf(v4.y - m) : 0.0f;
            float e2 = (c0 + 2 <= t) ? __expf(v4.z - m) : 0.0f;
            float e3 = (c0 + 3 <= t) ? __expf(v4.w - m) : 0.0f;
            float s = e0 + e1 + e2 + e3;
            #pragma unroll
            for (int off = 16; off > 0; off >>= 1)
                s += __shfl_xor_sync(0xffffffffu, s, off);

            // shfl reductions converge the warp: all loads of this row are
            // complete before any lane stores (in-place overwrite is safe).
            float inv = 1.0f / s;
            __half2* prow = reinterpret_cast<__half2*>(sp + t * SP_LD);
            prow[lane * 2 + 0] = __floats2half2_rn(e0 * inv, e1 * inv);
            prow[lane * 2 + 1] = __floats2half2_rn(e2 * inv, e3 * inv);
        }
        __syncthreads();

        // O = P @ v -> gmem
        #pragma unroll
        for (int i = 0; i < 2; i++)
            #pragma unroll
            for (int j = 0; j < 2; j++)
                wmma::fill_fragment(acc[i][j], 0.0f);

        #pragma unroll
        for (int kk = 0; kk < TT; kk += 16) {
            wmma::fragment<wmma::matrix_a, 16, 16, 16, __half, wmma::row_major> af[2];
            wmma::fragment<wmma::matrix_b, 16, 16, 16, __half, wmma::row_major> bf[2];
            #pragma unroll
            for (int i = 0; i < 2; i++)
                wmma::load_matrix_sync(af[i], sp + (wm2 * 32 + i * 16) * SP_LD + kk, SP_LD);
            #pragma unroll
            for (int j = 0; j < 2; j++)
                wmma::load_matrix_sync(bf[j], sv + kk * QK_LD + wn2 * 32 + j * 16, QK_LD);
            #pragma unroll
            for (int i = 0; i < 2; i++)
                #pragma unroll
                for (int j = 0; j < 2; j++)
                    wmma::mma_sync(acc[i][j], af[i], bf[j], acc[i][j]);
        }

        float* ob = out + (size_t)b * TT * HS;
        #pragma unroll
        for (int i = 0; i < 2; i++)
            #pragma unroll
            for (int j = 0; j < 2; j++)
                wmma::store_matrix_sync(ob + (wm2 * 32 + i * 16) * HS + wn2 * 32 + j * 16,
                                        acc[i][j], HS, wmma::mem_row_major);
    }
}

// ---------------------------------------------------------------------------
extern "C" void kernel_launch(void* const* d_in, const int* in_sizes, int n_in,
                              void* d_out, int out_size)
{
    const float* x  = (const float*)d_in[0];
    const float* Wq = (const float*)d_in[1];
    const float* Wk = (const float*)d_in[2];
    const float* Wv = (const float*)d_in[3];
    float* out = (float*)d_out;

    cudaFuncSetAttribute(fused_head_kernel, cudaFuncAttributeMaxDynamicSharedMemorySize, FUSED_SMEM);

    conv_wh_kernel<<<192, 256>>>(Wq, Wk, Wv);
    fused_head_kernel<<<NB, 512, FUSED_SMEM>>>(x, out);
}